// round 4
// baseline (speedup 1.0000x reference)
#include <cuda_runtime.h>

#define N_NODES 50000
#define N_EDGES 800000
#define SCAN_NB ((N_NODES + 255) / 256)   // 196 blocks

typedef unsigned long long ull;

// ---- packed fp32x2 helpers (sm_10x dual-issue fp32 via PTX) ----
__device__ __forceinline__ ull pack2(float lo, float hi) {
    ull r; asm("mov.b64 %0, {%1, %2};" : "=l"(r) : "f"(lo), "f"(hi)); return r;
}
__device__ __forceinline__ void fma2(ull& d, ull a, ull b) {
    asm("fma.rn.f32x2 %0, %1, %2, %0;" : "+l"(d) : "l"(a), "l"(b));
}
__device__ __forceinline__ ull add2(ull a, ull b) {
    ull r; asm("add.rn.f32x2 %0, %1, %2;" : "=l"(r) : "l"(a), "l"(b)); return r;
}

// ---- scratch (allocation-free: __device__ globals) ----
__device__ float g_deg  [N_NODES];
__device__ float g_dinv [N_NODES];
__device__ int   g_cnt  [N_NODES];
__device__ int   g_off  [N_NODES + 1];
__device__ int   g_cur  [N_NODES];
__device__ int   g_bsum [SCAN_NB];
__device__ int   g_srow [N_EDGES];
__device__ float g_snorm[N_EDGES];
__device__ float g_t  [N_NODES * 64];
__device__ float g_h  [N_NODES * 64];
__device__ float g_h2 [N_NODES * 64];

// ---------------------------------------------------------------------------
__global__ void zero_kernel() {
    int n = blockIdx.x * blockDim.x + threadIdx.x;
    if (n < N_NODES) { g_deg[n] = 0.0f; g_cnt[n] = 0; }
}

__global__ void hist_kernel(const int* __restrict__ row, const int* __restrict__ col) {
    int e = blockIdx.x * blockDim.x + threadIdx.x;
    if (e < N_EDGES) {
        atomicAdd(&g_deg[row[e]], 1.0f);
        atomicAdd(&g_cnt[col[e]], 1);
    }
}

// ---------------------------------------------------------------------------
__device__ __forceinline__ int block_excl_scan_256(int v, int tid) {
    int lane = tid & 31, wid = tid >> 5;
    int x = v;
#pragma unroll
    for (int d = 1; d < 32; d <<= 1) {
        int y = __shfl_up_sync(0xFFFFFFFFu, x, d);
        if (lane >= d) x += y;
    }
    __shared__ int wsum[8];
    if (lane == 31) wsum[wid] = x;
    __syncthreads();
    if (wid == 0) {
        int w = (lane < 8) ? wsum[lane] : 0;
#pragma unroll
        for (int d = 1; d < 8; d <<= 1) {
            int y = __shfl_up_sync(0xFFFFFFFFu, w, d);
            if (lane >= d) w += y;
        }
        if (lane < 8) wsum[lane] = w;
    }
    __syncthreads();
    int incl = x + (wid > 0 ? wsum[wid - 1] : 0);
    return incl - v;
}

__global__ void scan1_kernel() {
    int i = blockIdx.x * 256 + threadIdx.x;
    int v = (i < N_NODES) ? g_cnt[i] : 0;
    int excl = block_excl_scan_256(v, threadIdx.x);
    if (i < N_NODES) g_off[i] = excl;
    if (threadIdx.x == 255) g_bsum[blockIdx.x] = excl + v;
}

__global__ void scan2_kernel() {
    int t = threadIdx.x;
    int v = (t < SCAN_NB) ? g_bsum[t] : 0;
    int excl = block_excl_scan_256(v, t);
    if (t < SCAN_NB) g_bsum[t] = excl;
}

__global__ void scan3_kernel() {
    int i = blockIdx.x * 256 + threadIdx.x;
    if (i < N_NODES) {
        int o = g_off[i] + g_bsum[blockIdx.x];
        g_off[i] = o;
        g_cur[i] = o;
        float d = g_deg[i];
        g_dinv[i] = (d > 0.0f) ? rsqrtf(d) : 0.0f;
    }
    if (i == 0) g_off[N_NODES] = N_EDGES;
}

__global__ void build_kernel(const int* __restrict__ row, const int* __restrict__ col) {
    int e = blockIdx.x * blockDim.x + threadIdx.x;
    if (e < N_EDGES) {
        int r = row[e], c = col[e];
        int p = atomicAdd(&g_cur[c], 1);
        g_srow[p]  = r;
        g_snorm[p] = g_dinv[r] * g_dinv[c];
    }
}

// ---------------------------------------------------------------------------
// Fused dual GEMM with packed f32x2 FMAs:
//   T = A @ Wa,  H = A @ Wb + bias   (A: [N,64], W: [64,64])
// 64-row tile, 256 threads, 4 rows x 4 cols microtile; accumulators packed
// over column pairs so W loads come pre-packed from memory (ulonglong2).
__global__ void dual_gemm_kernel(const float* __restrict__ A,
                                 const float* __restrict__ Wa,
                                 const float* __restrict__ Wb,
                                 const float* __restrict__ bias,
                                 float* __restrict__ T,
                                 float* __restrict__ H) {
    __shared__ float xs[64][65];
    const int tid  = threadIdx.x;
    const int row0 = blockIdx.x * 64;

    for (int i = tid; i < 64 * 16; i += 256) {
        int r = i >> 4, c4 = i & 15;
        float4 v = make_float4(0.f, 0.f, 0.f, 0.f);
        int gr = row0 + r;
        if (gr < N_NODES) v = __ldg(reinterpret_cast<const float4*>(A) + gr * 16 + c4);
        xs[r][c4 * 4 + 0] = v.x; xs[r][c4 * 4 + 1] = v.y;
        xs[r][c4 * 4 + 2] = v.z; xs[r][c4 * 4 + 3] = v.w;
    }
    __syncthreads();

    const int tr = tid >> 4, tc = tid & 15;
    const int r0 = tr * 4, c0 = tc * 4;

    ull accA[4][2], accB[4][2];
#pragma unroll
    for (int i = 0; i < 4; i++)
#pragma unroll
        for (int j = 0; j < 2; j++) { accA[i][j] = 0ull; accB[i][j] = 0ull; }

#pragma unroll 8
    for (int k = 0; k < 64; k++) {
        ulonglong2 wa2 = __ldg(reinterpret_cast<const ulonglong2*>(Wa + k * 64 + c0));
        ulonglong2 wb2 = __ldg(reinterpret_cast<const ulonglong2*>(Wb + k * 64 + c0));
        ull xp0 = pack2(xs[r0 + 0][k], xs[r0 + 0][k]);
        ull xp1 = pack2(xs[r0 + 1][k], xs[r0 + 1][k]);
        ull xp2 = pack2(xs[r0 + 2][k], xs[r0 + 2][k]);
        ull xp3 = pack2(xs[r0 + 3][k], xs[r0 + 3][k]);
        fma2(accA[0][0], xp0, wa2.x); fma2(accA[0][1], xp0, wa2.y);
        fma2(accA[1][0], xp1, wa2.x); fma2(accA[1][1], xp1, wa2.y);
        fma2(accA[2][0], xp2, wa2.x); fma2(accA[2][1], xp2, wa2.y);
        fma2(accA[3][0], xp3, wa2.x); fma2(accA[3][1], xp3, wa2.y);
        fma2(accB[0][0], xp0, wb2.x); fma2(accB[0][1], xp0, wb2.y);
        fma2(accB[1][0], xp1, wb2.x); fma2(accB[1][1], xp1, wb2.y);
        fma2(accB[2][0], xp2, wb2.x); fma2(accB[2][1], xp2, wb2.y);
        fma2(accB[3][0], xp3, wb2.x); fma2(accB[3][1], xp3, wb2.y);
    }

    ulonglong2 bv = __ldg(reinterpret_cast<const ulonglong2*>(bias + c0));

#pragma unroll
    for (int i = 0; i < 4; i++) {
        int gr = row0 + r0 + i;
        if (gr < N_NODES) {
            ulonglong2 oa, ob;
            oa.x = accA[i][0];            oa.y = accA[i][1];
            ob.x = add2(accB[i][0], bv.x); ob.y = add2(accB[i][1], bv.y);
            *reinterpret_cast<ulonglong2*>(T + gr * 64 + c0) = oa;
            *reinterpret_cast<ulonglong2*>(H + gr * 64 + c0) = ob;
        }
    }
}

// Output GEMM: C[N,32] = A[N,64] @ W[64,32] + b, packed f32x2. 128 threads.
__global__ void out_gemm_kernel(const float* __restrict__ A,
                                const float* __restrict__ W,
                                const float* __restrict__ bias,
                                float* __restrict__ C) {
    __shared__ float xs[64][65];
    const int tid  = threadIdx.x;
    const int row0 = blockIdx.x * 64;

    for (int i = tid; i < 64 * 16; i += 128) {
        int r = i >> 4, c4 = i & 15;
        float4 v = make_float4(0.f, 0.f, 0.f, 0.f);
        int gr = row0 + r;
        if (gr < N_NODES) v = __ldg(reinterpret_cast<const float4*>(A) + gr * 16 + c4);
        xs[r][c4 * 4 + 0] = v.x; xs[r][c4 * 4 + 1] = v.y;
        xs[r][c4 * 4 + 2] = v.z; xs[r][c4 * 4 + 3] = v.w;
    }
    __syncthreads();

    const int tr = tid >> 3, tc = tid & 7;   // 16 x 8 thread grid
    const int r0 = tr * 4, c0 = tc * 4;

    ull acc[4][2];
#pragma unroll
    for (int i = 0; i < 4; i++) { acc[i][0] = 0ull; acc[i][1] = 0ull; }

#pragma unroll 8
    for (int k = 0; k < 64; k++) {
        ulonglong2 wv = __ldg(reinterpret_cast<const ulonglong2*>(W + k * 32 + c0));
        ull xp0 = pack2(xs[r0 + 0][k], xs[r0 + 0][k]);
        ull xp1 = pack2(xs[r0 + 1][k], xs[r0 + 1][k]);
        ull xp2 = pack2(xs[r0 + 2][k], xs[r0 + 2][k]);
        ull xp3 = pack2(xs[r0 + 3][k], xs[r0 + 3][k]);
        fma2(acc[0][0], xp0, wv.x); fma2(acc[0][1], xp0, wv.y);
        fma2(acc[1][0], xp1, wv.x); fma2(acc[1][1], xp1, wv.y);
        fma2(acc[2][0], xp2, wv.x); fma2(acc[2][1], xp2, wv.y);
        fma2(acc[3][0], xp3, wv.x); fma2(acc[3][1], xp3, wv.y);
    }

    ulonglong2 bv = __ldg(reinterpret_cast<const ulonglong2*>(bias + c0));
#pragma unroll
    for (int i = 0; i < 4; i++) {
        int gr = row0 + r0 + i;
        if (gr < N_NODES) {
            ulonglong2 o;
            o.x = add2(acc[i][0], bv.x);
            o.y = add2(acc[i][1], bv.y);
            *reinterpret_cast<ulonglong2*>(C + gr * 32 + c0) = o;
        }
    }
}

// ---------------------------------------------------------------------------
// CSR aggregation + ReLU, warp per node:
//   h[n] = relu(h[n] + sum_j snorm[j] * t[srow[j]])
// Lanes cooperatively load 32 edges' metadata (coalesced), broadcast via
// shuffle; each lane owns a float2 column slice of the 64-wide row.
__global__ void agg_kernel(const float* __restrict__ t, float* __restrict__ h) {
    int warp = (blockIdx.x * blockDim.x + threadIdx.x) >> 5;
    if (warp >= N_NODES) return;
    int lane = threadIdx.x & 31;

    int s = g_off[warp];
    int e = g_off[warp + 1];

    float2 acc = *reinterpret_cast<const float2*>(h + warp * 64 + lane * 2);

    for (int j0 = s; j0 < e; j0 += 32) {
        int jj = j0 + lane;
        int   r  = 0;
        float nv = 0.f;
        if (jj < e) { r = __ldg(&g_srow[jj]); nv = __ldg(&g_snorm[jj]); }
        int cnt = min(32, e - j0);
        for (int u = 0; u < cnt; u++) {
            int   rr = __shfl_sync(0xFFFFFFFFu, r,  u);
            float nn = __shfl_sync(0xFFFFFFFFu, nv, u);
            float2 v = __ldg(reinterpret_cast<const float2*>(t + rr * 64) + lane);
            acc.x = fmaf(v.x, nn, acc.x);
            acc.y = fmaf(v.y, nn, acc.y);
        }
    }

    acc.x = fmaxf(acc.x, 0.f);
    acc.y = fmaxf(acc.y, 0.f);
    *reinterpret_cast<float2*>(h + warp * 64 + lane * 2) = acc;
}

// ---------------------------------------------------------------------------
extern "C" void kernel_launch(void* const* d_in, const int* in_sizes, int n_in,
                              void* d_out, int out_size) {
    const float* x      = (const float*)d_in[0];
    const int*   ei     = (const int*)d_in[1];
    const int*   row    = ei;
    const int*   col    = ei + N_EDGES;
    const float* W_in1  = (const float*)d_in[2];
    const float* W_nb1  = (const float*)d_in[3];
    const float* b1     = (const float*)d_in[4];
    const float* W_in2  = (const float*)d_in[5];
    const float* W_nb2  = (const float*)d_in[6];
    const float* b2     = (const float*)d_in[7];
    const float* W_out  = (const float*)d_in[8];
    const float* b_out  = (const float*)d_in[9];
    float*       out    = (float*)d_out;

    float *t_p, *h_p, *h2_p;
    cudaGetSymbolAddress((void**)&t_p,  g_t);
    cudaGetSymbolAddress((void**)&h_p,  g_h);
    cudaGetSymbolAddress((void**)&h2_p, g_h2);

    const int TB = 256;
    const int node_blocks = (N_NODES + TB - 1) / TB;
    const int edge_blocks = (N_EDGES + TB - 1) / TB;
    const int gemm_blocks = (N_NODES + 63) / 64;
    const int agg_blocks  = (N_NODES * 32 + TB - 1) / TB;   // warp per node

    // prolog: degrees, CSR by target node (reused by both layers)
    zero_kernel<<<node_blocks, TB>>>();
    hist_kernel<<<edge_blocks, TB>>>(row, col);
    scan1_kernel<<<SCAN_NB, 256>>>();
    scan2_kernel<<<1, 256>>>();
    scan3_kernel<<<SCAN_NB, 256>>>();
    build_kernel<<<edge_blocks, TB>>>(row, col);

    // layer 1
    dual_gemm_kernel<<<gemm_blocks, 256>>>(x, W_nb1, W_in1, b1, t_p, h_p);
    agg_kernel<<<agg_blocks, TB>>>(t_p, h_p);

    // layer 2
    dual_gemm_kernel<<<gemm_blocks, 256>>>(h_p, W_nb2, W_in2, b2, t_p, h2_p);
    agg_kernel<<<agg_blocks, TB>>>(t_p, h2_p);

    // output projection
    out_gemm_kernel<<<gemm_blocks, 128>>>(h2_p, W_out, b_out, out);
}